// round 2
// baseline (speedup 1.0000x reference)
#include <cuda_runtime.h>
#include <math.h>

#define BB 4
#define CC 256
#define NN 4096

// scratch: q,k,v each [B][C][N] fp32 = 16.8 MB
__device__ float g_q[BB*CC*NN];
__device__ float g_k[BB*CC*NN];
__device__ float g_v[BB*CC*NN];

// ---------------------------------------------------------------------------
// Projection: O[b][o][n] = sum_c W[o][c] * X[b][c][n]
// grid: (256 tiles, 3 which, 4 batch), block 256
// ---------------------------------------------------------------------------
__global__ __launch_bounds__(256) void proj_kernel(
    const float* __restrict__ x, const float* __restrict__ y,
    const float* __restrict__ wq, const float* __restrict__ wk,
    const float* __restrict__ wv)
{
    __shared__ float w_s[64][68];   // [o_local][c_local]
    __shared__ float x_s[64][68];   // [c_local][n_local]

    int b = blockIdx.z;
    int which = blockIdx.y;
    const float* W = (which == 0) ? wq : ((which == 1) ? wk : wv);
    const float* X = (which == 0) ? x : y;
    float* O = (which == 0) ? g_q : ((which == 1) ? g_k : g_v);

    int o0 = (blockIdx.x >> 6) * 64;   // 4 o-tiles
    int n0 = (blockIdx.x & 63) * 64;   // 64 n-tiles
    const float* Xb = X + (size_t)b * CC * NN;
    float* Ob = O + (size_t)b * CC * NN;

    int t = threadIdx.x;
    int tn = t & 15;       // n sub-tile
    int to = t >> 4;       // o sub-tile

    float acc[4][4] = {};

    for (int c0 = 0; c0 < CC; c0 += 64) {
        __syncthreads();
        for (int idx = t; idx < 64 * 64; idx += 256) {
            int r = idx >> 6, cidx = idx & 63;
            w_s[r][cidx] = W[(size_t)(o0 + r) * CC + c0 + cidx];
            x_s[r][cidx] = Xb[(size_t)(c0 + r) * NN + n0 + cidx];
        }
        __syncthreads();
        #pragma unroll 16
        for (int cc = 0; cc < 64; cc++) {
            float4 xv = *(const float4*)&x_s[cc][tn * 4];
            float w0 = w_s[to * 4 + 0][cc];
            float w1 = w_s[to * 4 + 1][cc];
            float w2 = w_s[to * 4 + 2][cc];
            float w3 = w_s[to * 4 + 3][cc];
            acc[0][0] += w0 * xv.x; acc[0][1] += w0 * xv.y; acc[0][2] += w0 * xv.z; acc[0][3] += w0 * xv.w;
            acc[1][0] += w1 * xv.x; acc[1][1] += w1 * xv.y; acc[1][2] += w1 * xv.z; acc[1][3] += w1 * xv.w;
            acc[2][0] += w2 * xv.x; acc[2][1] += w2 * xv.y; acc[2][2] += w2 * xv.z; acc[2][3] += w2 * xv.w;
            acc[3][0] += w3 * xv.x; acc[3][1] += w3 * xv.y; acc[3][2] += w3 * xv.z; acc[3][3] += w3 * xv.w;
        }
    }

    #pragma unroll
    for (int r = 0; r < 4; r++) {
        float4 st;
        st.x = acc[r][0]; st.y = acc[r][1]; st.z = acc[r][2]; st.w = acc[r][3];
        *(float4*)&Ob[(size_t)(o0 + to * 4 + r) * NN + n0 + tn * 4] = st;
    }
}

// ---------------------------------------------------------------------------
// Flash attention + epilogue.
// grid: (N/64, B), block 256, dynamic smem ~170 KB
// ---------------------------------------------------------------------------
__global__ __launch_bounds__(256) void attn_kernel(
    const float* __restrict__ x, const float* __restrict__ gamma,
    float* __restrict__ out)
{
    extern __shared__ float smem[];
    float* q_s     = smem;                  // [256 o][64 i], stride 64
    float* k_s     = q_s + 256 * 64;        // [64 o][64 j], stride 64
    float* v_s     = k_s + 64 * 64;         // [256 c][j], stride 68
    float* p_s     = v_s + 256 * 68;        // [64 j][i], stride 68 (transposed P)
    float* red_s   = p_s + 64 * 68;         // [64 i][16 seg], stride 17
    float* m_s     = red_s + 64 * 17;       // [64]
    float* l_s     = m_s + 64;              // [64]
    float* scale_s = l_s + 64;              // [64]

    int b  = blockIdx.y;
    int i0 = blockIdx.x * 64;
    const float* qb = g_q + (size_t)b * CC * NN;
    const float* kb = g_k + (size_t)b * CC * NN;
    const float* vb = g_v + (size_t)b * CC * NN;

    int t = threadIdx.x;
    int ti = t & 15;       // S phase: i = ti*4..+3
    int tj = t >> 4;       // S phase: j = tj*4..+3
    int ii = t & 15;       // update: i = ii*4..+3
    int ci = t >> 4;       // update: c = ci*16..+15

    // load q tile (resident for whole block)
    for (int idx = t; idx < 256 * 64; idx += 256)
        q_s[idx] = qb[(size_t)(idx >> 6) * NN + i0 + (idx & 63)];
    if (t < 64) { m_s[t] = -3.0e38f; l_s[t] = 0.0f; }

    float acc[4][16] = {};   // [i sub-row][c sub-col]

    for (int jt = 0; jt < 64; jt++) {
        int j0 = jt * 64;

        // ---- S = q^T k over full C=256, in 4 chunks of 64 o ----
        float S[4][4] = {};
        for (int oc = 0; oc < 4; oc++) {
            __syncthreads();
            for (int idx = t; idx < 64 * 64; idx += 256)
                k_s[idx] = kb[(size_t)(oc * 64 + (idx >> 6)) * NN + j0 + (idx & 63)];
            if (oc == 0) {
                for (int idx = t; idx < 256 * 64; idx += 256)
                    v_s[(idx >> 6) * 68 + (idx & 63)] =
                        vb[(size_t)(idx >> 6) * NN + j0 + (idx & 63)];
            }
            __syncthreads();
            #pragma unroll 16
            for (int oo = 0; oo < 64; oo++) {
                float4 q4 = *(const float4*)&q_s[(oc * 64 + oo) * 64 + ti * 4];
                float4 k4 = *(const float4*)&k_s[oo * 64 + tj * 4];
                S[0][0] += q4.x * k4.x; S[0][1] += q4.x * k4.y; S[0][2] += q4.x * k4.z; S[0][3] += q4.x * k4.w;
                S[1][0] += q4.y * k4.x; S[1][1] += q4.y * k4.y; S[1][2] += q4.y * k4.z; S[1][3] += q4.y * k4.w;
                S[2][0] += q4.z * k4.x; S[2][1] += q4.z * k4.y; S[2][2] += q4.z * k4.z; S[2][3] += q4.z * k4.w;
                S[3][0] += q4.w * k4.x; S[3][1] += q4.w * k4.y; S[3][2] += q4.w * k4.z; S[3][3] += q4.w * k4.w;
            }
        }

        // ---- distributed online softmax ----
        // (a) per-thread row partial max
        #pragma unroll
        for (int a = 0; a < 4; a++) {
            float pm = fmaxf(fmaxf(S[a][0], S[a][1]), fmaxf(S[a][2], S[a][3]));
            red_s[(ti * 4 + a) * 17 + tj] = pm;
        }
        __syncthreads();
        // (b) row max / rescale factor
        if (t < 64) {
            float mold = m_s[t];
            float mx = mold;
            #pragma unroll
            for (int s = 0; s < 16; s++) mx = fmaxf(mx, red_s[t * 17 + s]);
            scale_s[t] = __expf(mold - mx);
            m_s[t] = mx;
        }
        __syncthreads();
        // (c) exp + write transposed P + partial row sums
        #pragma unroll
        for (int a = 0; a < 4; a++) {
            int i = ti * 4 + a;
            float mrow = m_s[i];
            float ps = 0.0f;
            #pragma unroll
            for (int bj = 0; bj < 4; bj++) {
                float p = __expf(S[a][bj] - mrow);
                p_s[(tj * 4 + bj) * 68 + i] = p;
                ps += p;
            }
            red_s[i * 17 + tj] = ps;
        }
        __syncthreads();
        // (d) fold partial sums into l (runs while others start the update)
        if (t < 64) {
            float l = l_s[t] * scale_s[t];
            #pragma unroll
            for (int s = 0; s < 16; s++) l += red_s[t * 17 + s];
            l_s[t] = l;
        }

        // ---- acc update: acc[i][c] = acc*scale + sum_j P[i][j] v[c][j] ----
        float sc0 = scale_s[ii * 4 + 0];
        float sc1 = scale_s[ii * 4 + 1];
        float sc2 = scale_s[ii * 4 + 2];
        float sc3 = scale_s[ii * 4 + 3];
        #pragma unroll
        for (int cc = 0; cc < 16; cc++) {
            acc[0][cc] *= sc0; acc[1][cc] *= sc1; acc[2][cc] *= sc2; acc[3][cc] *= sc3;
        }
        #pragma unroll 4
        for (int j = 0; j < 64; j++) {
            float4 p4 = *(const float4*)&p_s[j * 68 + ii * 4];
            #pragma unroll
            for (int cc = 0; cc < 16; cc++) {
                float vv = v_s[(ci * 16 + cc) * 68 + j];
                acc[0][cc] += p4.x * vv;
                acc[1][cc] += p4.y * vv;
                acc[2][cc] += p4.z * vv;
                acc[3][cc] += p4.w * vv;
            }
        }
    }

    __syncthreads();
    // epilogue: out = gamma * acc/l + x
    float g = gamma[0];
    float inv0 = 1.0f / l_s[ii * 4 + 0];
    float inv1 = 1.0f / l_s[ii * 4 + 1];
    float inv2 = 1.0f / l_s[ii * 4 + 2];
    float inv3 = 1.0f / l_s[ii * 4 + 3];
    #pragma unroll
    for (int cc = 0; cc < 16; cc++) {
        int c = ci * 16 + cc;
        size_t base = ((size_t)b * CC + c) * NN + i0 + ii * 4;
        float4 xv = *(const float4*)&x[base];
        float4 o4;
        o4.x = g * acc[0][cc] * inv0 + xv.x;
        o4.y = g * acc[1][cc] * inv1 + xv.y;
        o4.z = g * acc[2][cc] * inv2 + xv.z;
        o4.w = g * acc[3][cc] * inv3 + xv.w;
        *(float4*)&out[base] = o4;
    }
}

// ---------------------------------------------------------------------------
extern "C" void kernel_launch(void* const* d_in, const int* in_sizes, int n_in,
                              void* d_out, int out_size)
{
    const float* x     = (const float*)d_in[0];
    const float* y     = (const float*)d_in[1];
    const float* wq    = (const float*)d_in[2];
    const float* wk    = (const float*)d_in[3];
    const float* wv    = (const float*)d_in[4];
    const float* gamma = (const float*)d_in[5];
    float* out = (float*)d_out;

    dim3 g1(256, 3, 4);
    proj_kernel<<<g1, 256>>>(x, y, wq, wk, wv);

    size_t smem_bytes = (size_t)(256*64 + 64*64 + 256*68 + 64*68 + 64*17 + 3*64) * 4;
    cudaFuncSetAttribute(attn_kernel,
                         cudaFuncAttributeMaxDynamicSharedMemorySize,
                         (int)smem_bytes);
    dim3 g2(64, 4);
    attn_kernel<<<g2, 256, smem_bytes>>>(x, gamma, out);
}

// round 3
// speedup vs baseline: 1.0058x; 1.0058x over previous
#include <cuda_runtime.h>
#include <math.h>

#define BB 4
#define CC 256
#define NN 4096

// scratch: q,k,v each [B][C][N] fp32 = 16.8 MB
__device__ float g_q[BB*CC*NN];
__device__ float g_k[BB*CC*NN];
__device__ float g_v[BB*CC*NN];

// ---------------------------------------------------------------------------
// Projection: O[b][o][n] = sum_c W[o][c] * X[b][c][n]
// grid: (256 tiles, 3 which, 4 batch), block 256
// ---------------------------------------------------------------------------
__global__ __launch_bounds__(256) void proj_kernel(
    const float* __restrict__ x, const float* __restrict__ y,
    const float* __restrict__ wq, const float* __restrict__ wk,
    const float* __restrict__ wv)
{
    __shared__ float w_s[64][68];   // [o_local][c_local]
    __shared__ float x_s[64][68];   // [c_local][n_local]

    int b = blockIdx.z;
    int which = blockIdx.y;
    const float* W = (which == 0) ? wq : ((which == 1) ? wk : wv);
    const float* X = (which == 0) ? x : y;
    float* O = (which == 0) ? g_q : ((which == 1) ? g_k : g_v);

    int o0 = (blockIdx.x >> 6) * 64;   // 4 o-tiles
    int n0 = (blockIdx.x & 63) * 64;   // 64 n-tiles
    const float* Xb = X + (size_t)b * CC * NN;
    float* Ob = O + (size_t)b * CC * NN;

    int t = threadIdx.x;
    int tn = t & 15;       // n sub-tile
    int to = t >> 4;       // o sub-tile

    float acc[4][4] = {};

    for (int c0 = 0; c0 < CC; c0 += 64) {
        __syncthreads();
        for (int idx = t; idx < 64 * 64; idx += 256) {
            int r = idx >> 6, cidx = idx & 63;
            w_s[r][cidx] = W[(size_t)(o0 + r) * CC + c0 + cidx];
            x_s[r][cidx] = Xb[(size_t)(c0 + r) * NN + n0 + cidx];
        }
        __syncthreads();
        #pragma unroll 16
        for (int cc = 0; cc < 64; cc++) {
            float4 xv = *(const float4*)&x_s[cc][tn * 4];
            float w0 = w_s[to * 4 + 0][cc];
            float w1 = w_s[to * 4 + 1][cc];
            float w2 = w_s[to * 4 + 2][cc];
            float w3 = w_s[to * 4 + 3][cc];
            acc[0][0] += w0 * xv.x; acc[0][1] += w0 * xv.y; acc[0][2] += w0 * xv.z; acc[0][3] += w0 * xv.w;
            acc[1][0] += w1 * xv.x; acc[1][1] += w1 * xv.y; acc[1][2] += w1 * xv.z; acc[1][3] += w1 * xv.w;
            acc[2][0] += w2 * xv.x; acc[2][1] += w2 * xv.y; acc[2][2] += w2 * xv.z; acc[2][3] += w2 * xv.w;
            acc[3][0] += w3 * xv.x; acc[3][1] += w3 * xv.y; acc[3][2] += w3 * xv.z; acc[3][3] += w3 * xv.w;
        }
    }

    #pragma unroll
    for (int r = 0; r < 4; r++) {
        float4 st;
        st.x = acc[r][0]; st.y = acc[r][1]; st.z = acc[r][2]; st.w = acc[r][3];
        *(float4*)&Ob[(size_t)(o0 + to * 4 + r) * NN + n0 + tn * 4] = st;
    }
}

// ---------------------------------------------------------------------------
// Flash attention + epilogue.
// grid: (N/64, B), block 256, dynamic smem ~170 KB
// ---------------------------------------------------------------------------
__global__ __launch_bounds__(256) void attn_kernel(
    const float* __restrict__ x, const float* __restrict__ gamma,
    float* __restrict__ out)
{
    extern __shared__ float smem[];
    float* q_s     = smem;                  // [256 o][64 i], stride 64
    float* k_s     = q_s + 256 * 64;        // [64 o][64 j], stride 64
    float* v_s     = k_s + 64 * 64;         // [256 c][j], stride 68
    float* p_s     = v_s + 256 * 68;        // [64 j][i], stride 68 (transposed P)
    float* red_s   = p_s + 64 * 68;         // [64 i][16 seg], stride 17
    float* m_s     = red_s + 64 * 17;       // [64]
    float* l_s     = m_s + 64;              // [64]
    float* scale_s = l_s + 64;              // [64]

    int b  = blockIdx.y;
    int i0 = blockIdx.x * 64;
    const float* qb = g_q + (size_t)b * CC * NN;
    const float* kb = g_k + (size_t)b * CC * NN;
    const float* vb = g_v + (size_t)b * CC * NN;

    int t = threadIdx.x;
    int ti = t & 15;       // S phase: i = ti*4..+3
    int tj = t >> 4;       // S phase: j = tj*4..+3
    int ii = t & 15;       // update: i = ii*4..+3
    int ci = t >> 4;       // update: c = ci*16..+15

    // load q tile (resident for whole block)
    for (int idx = t; idx < 256 * 64; idx += 256)
        q_s[idx] = qb[(size_t)(idx >> 6) * NN + i0 + (idx & 63)];
    if (t < 64) { m_s[t] = -3.0e38f; l_s[t] = 0.0f; }

    float acc[4][16] = {};   // [i sub-row][c sub-col]

    for (int jt = 0; jt < 64; jt++) {
        int j0 = jt * 64;

        // ---- S = q^T k over full C=256, in 4 chunks of 64 o ----
        float S[4][4] = {};
        for (int oc = 0; oc < 4; oc++) {
            __syncthreads();
            for (int idx = t; idx < 64 * 64; idx += 256)
                k_s[idx] = kb[(size_t)(oc * 64 + (idx >> 6)) * NN + j0 + (idx & 63)];
            if (oc == 0) {
                for (int idx = t; idx < 256 * 64; idx += 256)
                    v_s[(idx >> 6) * 68 + (idx & 63)] =
                        vb[(size_t)(idx >> 6) * NN + j0 + (idx & 63)];
            }
            __syncthreads();
            #pragma unroll 16
            for (int oo = 0; oo < 64; oo++) {
                float4 q4 = *(const float4*)&q_s[(oc * 64 + oo) * 64 + ti * 4];
                float4 k4 = *(const float4*)&k_s[oo * 64 + tj * 4];
                S[0][0] += q4.x * k4.x; S[0][1] += q4.x * k4.y; S[0][2] += q4.x * k4.z; S[0][3] += q4.x * k4.w;
                S[1][0] += q4.y * k4.x; S[1][1] += q4.y * k4.y; S[1][2] += q4.y * k4.z; S[1][3] += q4.y * k4.w;
                S[2][0] += q4.z * k4.x; S[2][1] += q4.z * k4.y; S[2][2] += q4.z * k4.z; S[2][3] += q4.z * k4.w;
                S[3][0] += q4.w * k4.x; S[3][1] += q4.w * k4.y; S[3][2] += q4.w * k4.z; S[3][3] += q4.w * k4.w;
            }
        }

        // ---- distributed online softmax ----
        // (a) per-thread row partial max
        #pragma unroll
        for (int a = 0; a < 4; a++) {
            float pm = fmaxf(fmaxf(S[a][0], S[a][1]), fmaxf(S[a][2], S[a][3]));
            red_s[(ti * 4 + a) * 17 + tj] = pm;
        }
        __syncthreads();
        // (b) row max / rescale factor
        if (t < 64) {
            float mold = m_s[t];
            float mx = mold;
            #pragma unroll
            for (int s = 0; s < 16; s++) mx = fmaxf(mx, red_s[t * 17 + s]);
            scale_s[t] = __expf(mold - mx);
            m_s[t] = mx;
        }
        __syncthreads();
        // (c) exp + write transposed P + partial row sums
        #pragma unroll
        for (int a = 0; a < 4; a++) {
            int i = ti * 4 + a;
            float mrow = m_s[i];
            float ps = 0.0f;
            #pragma unroll
            for (int bj = 0; bj < 4; bj++) {
                float p = __expf(S[a][bj] - mrow);
                p_s[(tj * 4 + bj) * 68 + i] = p;
                ps += p;
            }
            red_s[i * 17 + tj] = ps;
        }
        __syncthreads();
        // (d) fold partial sums into l (runs while others start the update)
        if (t < 64) {
            float l = l_s[t] * scale_s[t];
            #pragma unroll
            for (int s = 0; s < 16; s++) l += red_s[t * 17 + s];
            l_s[t] = l;
        }

        // ---- acc update: acc[i][c] = acc*scale + sum_j P[i][j] v[c][j] ----
        float sc0 = scale_s[ii * 4 + 0];
        float sc1 = scale_s[ii * 4 + 1];
        float sc2 = scale_s[ii * 4 + 2];
        float sc3 = scale_s[ii * 4 + 3];
        #pragma unroll
        for (int cc = 0; cc < 16; cc++) {
            acc[0][cc] *= sc0; acc[1][cc] *= sc1; acc[2][cc] *= sc2; acc[3][cc] *= sc3;
        }
        #pragma unroll 4
        for (int j = 0; j < 64; j++) {
            float4 p4 = *(const float4*)&p_s[j * 68 + ii * 4];
            #pragma unroll
            for (int cc = 0; cc < 16; cc++) {
                float vv = v_s[(ci * 16 + cc) * 68 + j];
                acc[0][cc] += p4.x * vv;
                acc[1][cc] += p4.y * vv;
                acc[2][cc] += p4.z * vv;
                acc[3][cc] += p4.w * vv;
            }
        }
    }

    __syncthreads();
    // epilogue: out = gamma * acc/l + x
    float g = gamma[0];
    float inv0 = 1.0f / l_s[ii * 4 + 0];
    float inv1 = 1.0f / l_s[ii * 4 + 1];
    float inv2 = 1.0f / l_s[ii * 4 + 2];
    float inv3 = 1.0f / l_s[ii * 4 + 3];
    #pragma unroll
    for (int cc = 0; cc < 16; cc++) {
        int c = ci * 16 + cc;
        size_t base = ((size_t)b * CC + c) * NN + i0 + ii * 4;
        float4 xv = *(const float4*)&x[base];
        float4 o4;
        o4.x = g * acc[0][cc] * inv0 + xv.x;
        o4.y = g * acc[1][cc] * inv1 + xv.y;
        o4.z = g * acc[2][cc] * inv2 + xv.z;
        o4.w = g * acc[3][cc] * inv3 + xv.w;
        *(float4*)&out[base] = o4;
    }
}

// ---------------------------------------------------------------------------
extern "C" void kernel_launch(void* const* d_in, const int* in_sizes, int n_in,
                              void* d_out, int out_size)
{
    const float* x     = (const float*)d_in[0];
    const float* y     = (const float*)d_in[1];
    const float* wq    = (const float*)d_in[2];
    const float* wk    = (const float*)d_in[3];
    const float* wv    = (const float*)d_in[4];
    const float* gamma = (const float*)d_in[5];
    float* out = (float*)d_out;

    dim3 g1(256, 3, 4);
    proj_kernel<<<g1, 256>>>(x, y, wq, wk, wv);

    size_t smem_bytes = (size_t)(256*64 + 64*64 + 256*68 + 64*68 + 64*17 + 3*64) * 4;
    cudaFuncSetAttribute(attn_kernel,
                         cudaFuncAttributeMaxDynamicSharedMemorySize,
                         (int)smem_bytes);
    dim3 g2(64, 4);
    attn_kernel<<<g2, 256, smem_bytes>>>(x, gamma, out);
}